// round 11
// baseline (speedup 1.0000x reference)
#include <cuda_runtime.h>
#include <cstdint>
#include <math.h>

#ifndef M_PI
#define M_PI 3.14159265358979323846
#endif

// Problem dims
// B=16, C=32, N=512, T_IN=192, T_OUT=96, L_IN=97, L_OUT=49, E=64, LAYERS=2
constexpr int Mrows = 16 * 32 * 512;   // 262144 rows

// ---------------- scratch (__device__ globals; no allocation allowed) ----------
__device__ float d_bufA[(size_t)Mrows * 194];   // ~203 MB
__device__ float d_bufB[(size_t)Mrows * 194];   // ~203 MB
__device__ float d_bufC[(size_t)Mrows * 192];   // ~201 MB
__device__ float d_dft[192 * 194];
__device__ float d_idft[194 * 192];
__device__ float d_M1[32 * 192 * 192];
__device__ float d_M2[32 * 96 * 96];
__device__ float d_k1[32 * 192];
__device__ float d_k2[32 * 96];
__device__ float d_feat[16 * 192 * 32];
__device__ float d_qb[16 * 192 * 64];
__device__ float d_kb[16 * 192 * 64];
__device__ float d_gt[16 * 192];

__device__ __forceinline__ float gelu_t(float x) {
    // jax.nn.gelu default: tanh approximation
    float x3 = x * x * x;
    float t = tanhf(0.7978845608028654f * (x + 0.044715f * x3));
    return 0.5f * x * (1.0f + t);
}

// ---------------- precompute kernels -------------------------------------------

// dft[s][h2]  : h2<97 -> cos(2*pi*h*s/192) ; h2>=97 -> -sin(2*pi*(h2-97)*s/192)
// idft[r][t]  : r<97  -> c_h*cos ; r>=97 -> -c_h*sin ; c_h = 1/192 for h in {0,96} else 2/192
__global__ void k_dft(float* dft, float* idft) {
    int i = blockIdx.x * 256 + threadIdx.x;
    if (i >= 192 * 194) return;
    {
        int s = i / 194, h2 = i % 194;
        int h = (h2 < 97) ? h2 : h2 - 97;
        double ang = 2.0 * M_PI * (double)((s * h) % 192) / 192.0;
        dft[i] = (h2 < 97) ? (float)cos(ang) : (float)(-sin(ang));
    }
    {
        int r = i / 192, t = i % 192;       // 194*192 == 192*194 elements
        int h = (r < 97) ? r : r - 97;
        double ch = (h == 0 || h == 96) ? (1.0 / 192.0) : (2.0 / 192.0);
        double ang = 2.0 * M_PI * (double)((h * t) % 192) / 192.0;
        idft[i] = (r < 97) ? (float)(ch * cos(ang)) : (float)(-ch * sin(ang));
    }
}

// kker[c][t] = irfft(Wr + i*Wi)[t]  (time-domain circular-conv kernel)
__global__ void k_circ_k(const float* __restrict__ Wr, const float* __restrict__ Wi,
                         float* __restrict__ kk, int T, int L) {
    int i = blockIdx.x * 256 + threadIdx.x;
    if (i >= 32 * T) return;
    int c = i / T, t = i % T;
    double s = 0.0;
    for (int h = 0; h < L; h++) {
        double ch = (h == 0 || h == L - 1) ? 1.0 / (double)T : 2.0 / (double)T;
        double ang = 2.0 * M_PI * (double)((h * t) % T) / (double)T;
        s += ch * ((double)Wr[c * L + h] * cos(ang) - (double)Wi[c * L + h] * sin(ang));
    }
    kk[i] = (float)s;
}

// M[c][s][t] = kker[c][(t - s) mod T]  -> y[t] = sum_s u[s]*M[c][s][t]
__global__ void k_circ_m(const float* __restrict__ kk, float* __restrict__ Mm, int T) {
    int i = blockIdx.x * 256 + threadIdx.x;
    if (i >= 32 * T * T) return;
    int c = i / (T * T); int r = i % (T * T); int s = r / T, t = r % T;
    Mm[i] = kk[c * T + ((t - s + T) % T)];
}

// ---------------- spectrum channel-mix (freq_attn_in) --------------------------
// F,G layout: [b][c or l][n][194]  (0..96 real, 97..193 imag)
// G[b,l,n,h]     = Lc[l,h] * sum_c Gc[c,l] * F_re[b,c,n,h]
// G[b,l,n,97+h]  = Lt[l,h] * sum_c Gt[c,l] * F_im[b,c,n,h]
__global__ void k_mix(const float* __restrict__ F, float* __restrict__ G,
                      const float* __restrict__ Gc, const float* __restrict__ Lc,
                      const float* __restrict__ Gt, const float* __restrict__ Lt) {
    __shared__ float sF[32][195];
    __shared__ float sGc[32][32];
    __shared__ float sGt[32][32];
    int b = blockIdx.x >> 9;
    int n = blockIdx.x & 511;
    int tid = threadIdx.x;
    for (int idx = tid; idx < 32 * 194; idx += 256) {
        int c = idx / 194, h = idx % 194;
        sF[c][h] = F[(((size_t)b * 32 + c) * 512 + n) * 194 + h];
    }
    for (int idx = tid; idx < 1024; idx += 256) {
        sGc[idx >> 5][idx & 31] = Gc[idx];
        sGt[idx >> 5][idx & 31] = Gt[idx];
    }
    __syncthreads();
    for (int o = tid; o < 32 * 194; o += 256) {
        int l = o / 194, h2 = o % 194;
        float s = 0.f;
        if (h2 < 97) {
            #pragma unroll 8
            for (int c = 0; c < 32; c++) s = fmaf(sGc[c][l], sF[c][h2], s);
            s *= Lc[l * 97 + h2];
        } else {
            int h = h2 - 97;
            #pragma unroll 8
            for (int c = 0; c < 32; c++) s = fmaf(sGt[c][l], sF[c][h2], s);
            s *= Lt[l * 97 + h];
        }
        G[(((size_t)b * 32 + l) * 512 + n) * 194 + h2] = s;
    }
}

// ---------------- attention-gate helpers ---------------------------------------

// feat[b][t][c] = mean_n Z[b][c][n][t]
__global__ void k_feat(const float* __restrict__ Z, float* __restrict__ feat, int T) {
    int b = blockIdx.x >> 5, c = blockIdx.x & 31;
    int t = threadIdx.x;
    const float* p = Z + ((size_t)(b * 32 + c) * 512) * T + t;
    float s = 0.f;
    #pragma unroll 4
    for (int n = 0; n < 512; n++) s += p[(size_t)n * T];
    feat[((size_t)b * T + t) * 32 + c] = s * (1.0f / 512.0f);
}

// q[b][t][e], k[b][t][e] from feat @ Wq / Wk  (W: [32][64])
__global__ void k_qk(const float* __restrict__ feat, const float* __restrict__ Wq,
                     const float* __restrict__ Wk, float* __restrict__ qo,
                     float* __restrict__ ko, int T) {
    int b = blockIdx.x;
    __shared__ float sW[32][128];
    int tid = threadIdx.x;
    for (int i = tid; i < 2048; i += 256) {
        int c = i >> 6, e = i & 63;
        sW[c][e] = Wq[i]; sW[c][64 + e] = Wk[i];
    }
    __syncthreads();
    for (int o = tid; o < T * 64; o += 256) {
        int t = o >> 6, e = o & 63;
        const float* f = feat + ((size_t)b * T + t) * 32;
        float sq = 0.f, sk = 0.f;
        #pragma unroll
        for (int c = 0; c < 32; c++) {
            float fv = f[c];
            sq = fmaf(fv, sW[c][e], sq);
            sk = fmaf(fv, sW[c][64 + e], sk);
        }
        qo[(size_t)b * T * 64 + o] = sq;
        ko[(size_t)b * T * 64 + o] = sk;
    }
}

// g[b][t] = gelu( softmax_row(q_t . k_j / 8)[t] )   (diagonal only, online softmax)
__global__ void k_gate(const float* __restrict__ qv, const float* __restrict__ kv,
                       float* __restrict__ g, int T) {
    int b = blockIdx.x, t = threadIdx.x;
    float qr[64];
    const float* qp = qv + ((size_t)b * T + t) * 64;
    #pragma unroll
    for (int e = 0; e < 64; e++) qr[e] = qp[e];
    const float* kb = kv + (size_t)b * T * 64;
    float mx = -3.0e38f, sum = 0.f, sd = 0.f;
    for (int j = 0; j < T; j++) {
        float s = 0.f;
        #pragma unroll
        for (int e = 0; e < 64; e++) s = fmaf(qr[e], kb[j * 64 + e], s);
        s *= 0.125f;
        if (j == t) sd = s;
        float nmx = fmaxf(mx, s);
        sum = sum * expf(mx - nmx) + expf(s - nmx);
        mx = nmx;
    }
    float w = expf(sd - mx) / sum;
    g[b * T + t] = gelu_t(w);
}

// ---------------- generic fused GEMM -------------------------------------------
// out[m][j] = epi( sum_k a(m,k) * B[k][j] )
//   a(m,k) = A[m,k] * (HAS_GATE ? 1+g[b,k] : 1) + (HAS_A2 ? A2[m,k] : 0)
//   B per-channel (PER_CH_B): B += c*K*Nn,  c from row block (rows share (b,c))
//   EPI: 0 none | 1 +P[m,j] | 2 +bias[j] | 3 P[m,j]*gelu(acc)
constexpr int BM = 128, BN = 64, BK = 16;

template<int EPI, bool HAS_A2, bool PER_CH_B, bool HAS_GATE>
__global__ __launch_bounds__(256)
void gemm_k(const float* __restrict__ A, const float* __restrict__ A2,
            const float* __restrict__ gate, const float* __restrict__ Bm,
            const float* __restrict__ P, const float* __restrict__ bias,
            float* __restrict__ out, int K, int Nn) {
    __shared__ float As[BK][BM + 4];
    __shared__ float Bs[BK][BN + 4];
    __shared__ float sAk[224];

    const int tid = threadIdx.x;
    const int m0 = blockIdx.y * BM;
    const int n0 = blockIdx.x * BN;
    const int bc = m0 >> 9;     // row / 512 nodes
    const int c  = bc & 31;
    const int b  = bc >> 5;

    if (HAS_GATE) {
        for (int k = tid; k < K; k += 256) sAk[k] = 1.f + gate[b * K + k];
        __syncthreads();
    }
    const float* Bp = Bm;
    if (PER_CH_B) Bp += (size_t)c * K * Nn;

    float acc[8][4];
    #pragma unroll
    for (int i = 0; i < 8; i++)
        #pragma unroll
        for (int j = 0; j < 4; j++) acc[i][j] = 0.f;

    const int a_k = tid & 15;
    const int a_m = tid >> 4;     // 0..15
    const int b_j = tid & 63;
    const int b_k = tid >> 6;     // 0..3
    const int rg = tid >> 4;      // row group 0..15
    const int cg = tid & 15;      // col group 0..15

    const int nkt = (K + BK - 1) / BK;
    for (int kt = 0; kt < nkt; kt++) {
        const int kb = kt * BK;
        {
            const int gk = kb + a_k;
            const bool okk = (gk < K);
            float sc = 1.f;
            if (HAS_GATE) sc = okk ? sAk[gk] : 0.f;
            #pragma unroll
            for (int i = 0; i < 8; i++) {
                const int m = a_m + (i << 4);
                float v = 0.f;
                if (okk) {
                    size_t idx = (size_t)(m0 + m) * K + gk;
                    v = A[idx];
                    if (HAS_GATE) v *= sc;
                    if (HAS_A2) v += A2[idx];
                }
                As[a_k][m] = v;
            }
        }
        #pragma unroll
        for (int i = 0; i < 4; i++) {
            const int kk2 = b_k + (i << 2);
            const int gk = kb + kk2;
            const int gj = n0 + b_j;
            float v = 0.f;
            if (gk < K && gj < Nn) v = Bp[(size_t)gk * Nn + gj];
            Bs[kk2][b_j] = v;
        }
        __syncthreads();
        #pragma unroll
        for (int k = 0; k < BK; k++) {
            float ra[8], rb[4];
            #pragma unroll
            for (int i = 0; i < 8; i++) ra[i] = As[k][(rg << 3) + i];
            #pragma unroll
            for (int j = 0; j < 4; j++) rb[j] = Bs[k][cg + (j << 4)];
            #pragma unroll
            for (int i = 0; i < 8; i++)
                #pragma unroll
                for (int j = 0; j < 4; j++)
                    acc[i][j] = fmaf(ra[i], rb[j], acc[i][j]);
        }
        __syncthreads();
    }
    #pragma unroll
    for (int i = 0; i < 8; i++) {
        const int m = m0 + (rg << 3) + i;
        #pragma unroll
        for (int j = 0; j < 4; j++) {
            const int jj = n0 + cg + (j << 4);
            if (jj < Nn) {
                size_t o = (size_t)m * Nn + jj;
                float v = acc[i][j];
                if (EPI == 1) v += P[o];
                else if (EPI == 2) v += bias[jj];
                else if (EPI == 3) v = P[o] * gelu_t(v);
                out[o] = v;
            }
        }
    }
}

// ---------------- host orchestration -------------------------------------------

static float* symaddr(const void* s) {
    void* p = nullptr;
    cudaGetSymbolAddress(&p, s);
    return (float*)p;
}

extern "C" void kernel_launch(void* const* d_in, const int* in_sizes, int n_in,
                              void* d_out, int out_size) {
    const float* x   = (const float*)d_in[0];
    const float* Gc  = (const float*)d_in[3];
    const float* Lc  = (const float*)d_in[4];
    const float* Gt  = (const float*)d_in[5];
    const float* Lt  = (const float*)d_in[6];
    const float* f1r = (const float*)d_in[7];
    const float* f1i = (const float*)d_in[8];
    const float* f2r = (const float*)d_in[9];
    const float* f2i = (const float*)d_in[10];
    const float* fcW = (const float*)d_in[11];
    const float* fcb = (const float*)d_in[12];
    const float* mi1 = (const float*)d_in[13];
    const float* mi2 = (const float*)d_in[14];
    const float* mo1 = (const float*)d_in[15];
    const float* mo2 = (const float*)d_in[16];
    const float* aiq = (const float*)d_in[17];
    const float* aik = (const float*)d_in[18];
    const float* aoq = (const float*)d_in[19];
    const float* aok = (const float*)d_in[20];
    float* out = (float*)d_out;

    float* pA   = symaddr(d_bufA);
    float* pB   = symaddr(d_bufB);
    float* pC   = symaddr(d_bufC);
    float* pdft = symaddr(d_dft);
    float* pidf = symaddr(d_idft);
    float* pM1  = symaddr(d_M1);
    float* pM2  = symaddr(d_M2);
    float* pk1  = symaddr(d_k1);
    float* pk2  = symaddr(d_k2);
    float* pft  = symaddr(d_feat);
    float* pq   = symaddr(d_qb);
    float* pk   = symaddr(d_kb);
    float* pg   = symaddr(d_gt);

    const dim3 T256(256);
    const dim3 G194(4, Mrows / BM);
    const dim3 G192(3, Mrows / BM);
    const dim3 G96(2, Mrows / BM);

    // ---- precompute constant operators (cheap) ----
    k_dft<<<(192 * 194 + 255) / 256, 256>>>(pdft, pidf);
    k_circ_k<<<(32 * 192 + 255) / 256, 256>>>(f1r, f1i, pk1, 192, 97);
    k_circ_m<<<(32 * 192 * 192 + 255) / 256, 256>>>(pk1, pM1, 192);
    k_circ_k<<<(32 * 96 + 255) / 256, 256>>>(f2r, f2i, pk2, 96, 49);
    k_circ_m<<<(32 * 96 * 96 + 255) / 256, 256>>>(pk2, pM2, 96);

    // ---- freq_attn_in: F = rfft(x); mix; x_c = x + irfft(mix) ----
    gemm_k<0, false, false, false><<<G194, T256>>>(x, nullptr, nullptr, pdft,
                                                   nullptr, nullptr, pA, 192, 194);
    k_mix<<<16 * 512, 256>>>(pA, pB, Gc, Lc, Gt, Lt);
    gemm_k<1, false, false, false><<<G192, T256>>>(pB, nullptr, nullptr, pidf,
                                                   x, nullptr, pC, 194, 192);

    // ---- input layer 0: gmlp then gate (gate folded into next GEMM loads) ----
    gemm_k<0, false, false, false><<<G192, T256>>>(pC, nullptr, nullptr, mi1,
                                                   nullptr, nullptr, pA, 192, 192);
    gemm_k<3, false, false, false><<<G192, T256>>>(pC, nullptr, nullptr, mi2,
                                                   pA, nullptr, pB, 192, 192);
    k_feat<<<512, 192>>>(pB, pft, 192);
    k_qk<<<16, 256>>>(pft, aiq, aik, pq, pk, 192);
    k_gate<<<16, 192>>>(pq, pk, pg, 192);

    // ---- input layer 1 (A scaled by 1+g0) ----
    gemm_k<0, false, false, true><<<G192, T256>>>(pB, nullptr, pg, mi1 + 192 * 192,
                                                  nullptr, nullptr, pC, 192, 192);
    gemm_k<3, false, false, true><<<G192, T256>>>(pB, nullptr, pg, mi2 + 192 * 192,
                                                  pC, nullptr, pA, 192, 192);
    k_feat<<<512, 192>>>(pA, pft, 192);
    k_qk<<<16, 256>>>(pft, aiq + 32 * 64, aik + 32 * 64, pq, pk, 192);
    k_gate<<<16, 192>>>(pq, pk, pg, 192);

    // ---- fconv1: h_x = circconv(x + x_c*(1+g1), M1_c) ----
    gemm_k<0, true, true, true><<<G192, T256>>>(pA, x, pg, pM1,
                                                nullptr, nullptr, pB, 192, 192);

    // ---- fc_idp: h_y = h_x @ Wfc + b ----
    gemm_k<2, false, false, false><<<G96, T256>>>(pB, nullptr, nullptr, fcW,
                                                  nullptr, fcb, pC, 192, 96);

    // ---- output layer 0 ----
    gemm_k<0, false, false, false><<<G96, T256>>>(pC, nullptr, nullptr, mo1,
                                                  nullptr, nullptr, pA, 96, 96);
    gemm_k<3, false, false, false><<<G96, T256>>>(pC, nullptr, nullptr, mo2,
                                                  pA, nullptr, pB, 96, 96);
    k_feat<<<512, 96>>>(pB, pft, 96);
    k_qk<<<16, 256>>>(pft, aoq, aok, pq, pk, 96);
    k_gate<<<16, 96>>>(pq, pk, pg, 96);

    // ---- output layer 1 (A scaled by 1+g2); second GEMM writes bufA in place ----
    gemm_k<0, false, false, true><<<G96, T256>>>(pB, nullptr, pg, mo1 + 96 * 96,
                                                 nullptr, nullptr, pA, 96, 96);
    gemm_k<3, false, false, true><<<G96, T256>>>(pB, nullptr, pg, mo2 + 96 * 96,
                                                 pA, nullptr, pA, 96, 96);
    k_feat<<<512, 96>>>(pA, pft, 96);
    k_qk<<<16, 256>>>(pft, aoq + 32 * 64, aok + 32 * 64, pq, pk, 96);
    k_gate<<<16, 96>>>(pq, pk, pg, 96);

    // ---- final fconv2: out = circconv(h_y + y_c*(1+g3), M2_c) ----
    gemm_k<0, true, true, true><<<G96, T256>>>(pA, pC, pg, pM2,
                                               nullptr, nullptr, out, 96, 96);
}

// round 13
// speedup vs baseline: 1.6743x; 1.6743x over previous
#include <cuda_runtime.h>
#include <cstdint>
#include <math.h>

#ifndef M_PI
#define M_PI 3.14159265358979323846
#endif

// Problem dims: B=16, C=32, N=512, T_IN=192, T_OUT=96, L_IN=97, L_OUT=49, E=64
constexpr int Mrows = 16 * 32 * 512;   // 262144 rows
constexpr int LF = 196;                // padded spectral width (194 -> 196 for 16B alignment)

// ---------------- scratch (__device__ globals; no allocation allowed) ----------
__device__ float d_bufA[(size_t)Mrows * LF];    // ~205 MB
__device__ float d_bufB[(size_t)Mrows * LF];    // ~205 MB
__device__ float d_bufC[(size_t)Mrows * 192];   // ~201 MB
__device__ float d_dft[192 * LF];
__device__ float d_idft[LF * 192];
__device__ float d_M1[32 * 192 * 192];
__device__ float d_M2[32 * 96 * 96];
__device__ float d_k1[32 * 192];
__device__ float d_k2[32 * 96];
__device__ float d_feat[16 * 192 * 32];
__device__ float d_qb[16 * 192 * 64];
__device__ float d_kb[16 * 192 * 64];
__device__ float d_gt[16 * 192];

__device__ __forceinline__ float gelu_t(float x) {
    // jax.nn.gelu default: tanh approximation
    float x3 = x * x * x;
    float t = tanhf(0.7978845608028654f * (x + 0.044715f * x3));
    return 0.5f * x * (1.0f + t);
}

__device__ __forceinline__ float to_tf32(float x) {
    uint32_t u;
    asm("cvt.rna.tf32.f32 %0, %1;" : "=r"(u) : "f"(x));
    return __uint_as_float(u);
}

__device__ __forceinline__ void mma_tf32(float* c, const uint32_t* a, const uint32_t* b) {
    asm volatile(
        "mma.sync.aligned.m16n8k8.row.col.f32.tf32.tf32.f32 "
        "{%0,%1,%2,%3}, {%4,%5,%6,%7}, {%8,%9}, {%0,%1,%2,%3};"
        : "+f"(c[0]), "+f"(c[1]), "+f"(c[2]), "+f"(c[3])
        : "r"(a[0]), "r"(a[1]), "r"(a[2]), "r"(a[3]), "r"(b[0]), "r"(b[1]));
}

// ---------------- precompute kernels (float trig; was dominant double-trig cost) -----

// dft[192][196]: h2<97 -> cos(2*pi*h*s/192) ; 97<=h2<194 -> -sin ; pad 0
// idft[196][192]: r<97 -> c_h*cos ; 97<=r<194 -> -c_h*sin ; pad rows 0
__global__ void k_dft(float* dft, float* idft) {
    int i = blockIdx.x * 256 + threadIdx.x;
    if (i >= 192 * LF) return;
    {
        int s = i / LF, h2 = i % LF;
        float v = 0.f;
        if (h2 < 194) {
            int h = (h2 < 97) ? h2 : h2 - 97;
            float fr = (float)(2 * ((s * h) % 192)) / 192.0f;
            float sn, cs; sincospif(fr, &sn, &cs);
            v = (h2 < 97) ? cs : -sn;
        }
        dft[i] = v;
    }
    {
        int r = i / 192, t = i % 192;     // LF*192 == 192*LF elements
        float v = 0.f;
        if (r < 194) {
            int h = (r < 97) ? r : r - 97;
            float ch = (h == 0 || h == 96) ? (1.f / 192.f) : (2.f / 192.f);
            float fr = (float)(2 * ((h * t) % 192)) / 192.0f;
            float sn, cs; sincospif(fr, &sn, &cs);
            v = (r < 97) ? ch * cs : -ch * sn;
        }
        idft[i] = v;
    }
}

// kker[c][t] = irfft(Wr + i*Wi)[t]
__global__ void k_circ_k(const float* __restrict__ Wr, const float* __restrict__ Wi,
                         float* __restrict__ kk, int T, int L) {
    int i = blockIdx.x * 256 + threadIdx.x;
    if (i >= 32 * T) return;
    int c = i / T, t = i % T;
    float s = 0.f;
    for (int h = 0; h < L; h++) {
        float ch = (h == 0 || h == L - 1) ? 1.f / (float)T : 2.f / (float)T;
        float fr = (float)(2 * ((h * t) % T)) / (float)T;
        float sn, cs; sincospif(fr, &sn, &cs);
        s += ch * (Wr[c * L + h] * cs - Wi[c * L + h] * sn);
    }
    kk[i] = s;
}

// M[c][s][t] = kker[c][(t - s) mod T]
__global__ void k_circ_m(const float* __restrict__ kk, float* __restrict__ Mm, int T) {
    int i = blockIdx.x * 256 + threadIdx.x;
    if (i >= 32 * T * T) return;
    int c = i / (T * T); int r = i % (T * T); int s = r / T, t = r % T;
    Mm[i] = kk[c * T + ((t - s + T) % T)];
}

// ---------------- spectrum channel-mix (freq_attn_in), stride LF=196 ----------------
__global__ void k_mix(const float* __restrict__ F, float* __restrict__ G,
                      const float* __restrict__ Gc, const float* __restrict__ Lc,
                      const float* __restrict__ Gt, const float* __restrict__ Lt) {
    __shared__ float sF[32][195];
    __shared__ float sGc[32][32];
    __shared__ float sGt[32][32];
    int b = blockIdx.x >> 9;
    int n = blockIdx.x & 511;
    int tid = threadIdx.x;
    for (int idx = tid; idx < 32 * 194; idx += 256) {
        int c = idx / 194, h = idx % 194;
        sF[c][h] = F[(((size_t)b * 32 + c) * 512 + n) * LF + h];
    }
    for (int idx = tid; idx < 1024; idx += 256) {
        sGc[idx >> 5][idx & 31] = Gc[idx];
        sGt[idx >> 5][idx & 31] = Gt[idx];
    }
    __syncthreads();
    for (int o = tid; o < 32 * LF; o += 256) {
        int l = o / LF, h2 = o % LF;
        float s = 0.f;
        if (h2 < 97) {
            #pragma unroll 8
            for (int c = 0; c < 32; c++) s = fmaf(sGc[c][l], sF[c][h2], s);
            s *= Lc[l * 97 + h2];
        } else if (h2 < 194) {
            int h = h2 - 97;
            #pragma unroll 8
            for (int c = 0; c < 32; c++) s = fmaf(sGt[c][l], sF[c][h2], s);
            s *= Lt[l * 97 + h];
        }
        G[(((size_t)b * 32 + l) * 512 + n) * LF + h2] = s;
    }
}

// ---------------- attention-gate helpers --------------------------------------------

__global__ void k_feat(const float* __restrict__ Z, float* __restrict__ feat, int T) {
    int b = blockIdx.x >> 5, c = blockIdx.x & 31;
    int t = threadIdx.x;
    const float* p = Z + ((size_t)(b * 32 + c) * 512) * T + t;
    float s = 0.f;
    #pragma unroll 4
    for (int n = 0; n < 512; n++) s += p[(size_t)n * T];
    feat[((size_t)b * T + t) * 32 + c] = s * (1.0f / 512.0f);
}

__global__ void k_qk(const float* __restrict__ feat, const float* __restrict__ Wq,
                     const float* __restrict__ Wk, float* __restrict__ qo,
                     float* __restrict__ ko, int T) {
    int b = blockIdx.x;
    __shared__ float sW[32][128];
    int tid = threadIdx.x;
    for (int i = tid; i < 2048; i += 256) {
        int c = i >> 6, e = i & 63;
        sW[c][e] = Wq[i]; sW[c][64 + e] = Wk[i];
    }
    __syncthreads();
    for (int o = tid; o < T * 64; o += 256) {
        int t = o >> 6, e = o & 63;
        const float* f = feat + ((size_t)b * T + t) * 32;
        float sq = 0.f, sk = 0.f;
        #pragma unroll
        for (int c = 0; c < 32; c++) {
            float fv = f[c];
            sq = fmaf(fv, sW[c][e], sq);
            sk = fmaf(fv, sW[c][64 + e], sk);
        }
        qo[(size_t)b * T * 64 + o] = sq;
        ko[(size_t)b * T * 64 + o] = sk;
    }
}

__global__ void k_gate(const float* __restrict__ qv, const float* __restrict__ kv,
                       float* __restrict__ g, int T) {
    int b = blockIdx.x, t = threadIdx.x;
    float qr[64];
    const float* qp = qv + ((size_t)b * T + t) * 64;
    #pragma unroll
    for (int e = 0; e < 64; e++) qr[e] = qp[e];
    const float* kb = kv + (size_t)b * T * 64;
    float mx = -3.0e38f, sum = 0.f, sd = 0.f;
    for (int j = 0; j < T; j++) {
        float s = 0.f;
        #pragma unroll
        for (int e = 0; e < 64; e++) s = fmaf(qr[e], kb[j * 64 + e], s);
        s *= 0.125f;
        if (j == t) sd = s;
        float nmx = fmaxf(mx, s);
        sum = sum * expf(mx - nmx) + expf(s - nmx);
        mx = nmx;
    }
    float w = expf(sd - mx) / sum;
    g[b * T + t] = gelu_t(w);
}

// ---------------- tf32 tensor-core fused GEMM ----------------------------------------
// out[m][j] = epi( sum_k a(m,k) * B[k][j] )
//   a(m,k) = A[m,k] * (HAS_GATE ? 1+g[b,k] : 1) + (HAS_A2 ? A2[m,k] : 0)
//   PER_CH_B: B += c*K*Nn (c from row block; 128 rows share (b,c))
//   EPI: 0 none | 1 +P | 2 +bias[j] | 3 P*gelu(acc)
// Tile: BM=128, BN=64, BK=32; 256 threads = 8 warps (4 m x 2 n), warp tile 32x32.
// Requires K % 4 == 0 and Nn even (true for 192/196/96).
constexpr int BM = 128, BN = 64, BK = 32;

template<int EPI, bool HAS_A2, bool PER_CH_B, bool HAS_GATE>
__global__ __launch_bounds__(256)
void gemm_tc(const float* __restrict__ A, const float* __restrict__ A2,
             const float* __restrict__ gate, const float* __restrict__ Bm,
             const float* __restrict__ P, const float* __restrict__ bias,
             float* __restrict__ out, int K, int Nn) {
    __shared__ float As[BM][36];   // row-major, stride 36: conflict-free frag fetch
    __shared__ float Bs[BK][72];   // row-major, stride 72: conflict-free frag fetch
    __shared__ float sAk[224];

    const int tid = threadIdx.x;
    const int m0 = blockIdx.y * BM;
    const int n0 = blockIdx.x * BN;
    const int bc = m0 >> 9;
    const int c  = bc & 31;
    const int b  = bc >> 5;

    if (HAS_GATE) {
        for (int k2 = tid; k2 < K; k2 += 256) sAk[k2] = 1.f + gate[b * K + k2];
        __syncthreads();
    }
    const float* Bp = PER_CH_B ? (Bm + (size_t)c * K * Nn) : Bm;

    const int lane = tid & 31, warp = tid >> 5;
    const int wm = warp >> 1, wn = warp & 1;       // 4 x 2 warp grid
    const int g = lane >> 2, t4 = lane & 3;

    // global->reg loader mapping
    const int a_kq = tid & 7, a_m = tid >> 3;      // A: rows a_m+32i, float4 at k=a_kq*4
    const int b_j4 = tid & 15, b_k = tid >> 4;     // B: rows b_k, b_k+16; float4 at j=b_j4*4

    float4 ra[4];
    float4 rb[2];

    auto ldA = [&](int kb) {
        const int gk = kb + a_kq * 4;
        const bool full = (gk + 3 < K);
        #pragma unroll
        for (int i = 0; i < 4; i++) {
            const size_t row = (size_t)(m0 + a_m + 32 * i);
            const float* p = A + row * K + gk;
            float4 v = make_float4(0.f, 0.f, 0.f, 0.f);
            if (full) v = *(const float4*)p;
            else {
                if (gk     < K) v.x = p[0];
                if (gk + 1 < K) v.y = p[1];
                if (gk + 2 < K) v.z = p[2];
                if (gk + 3 < K) v.w = p[3];
            }
            if (HAS_GATE) {
                if (full) { v.x *= sAk[gk]; v.y *= sAk[gk+1]; v.z *= sAk[gk+2]; v.w *= sAk[gk+3]; }
                else {
                    if (gk     < K) v.x *= sAk[gk];
                    if (gk + 1 < K) v.y *= sAk[gk+1];
                    if (gk + 2 < K) v.z *= sAk[gk+2];
                    if (gk + 3 < K) v.w *= sAk[gk+3];
                }
            }
            if (HAS_A2) {
                const float* p2 = A2 + row * K + gk;
                if (full) { float4 w = *(const float4*)p2; v.x += w.x; v.y += w.y; v.z += w.z; v.w += w.w; }
                else {
                    if (gk     < K) v.x += p2[0];
                    if (gk + 1 < K) v.y += p2[1];
                    if (gk + 2 < K) v.z += p2[2];
                    if (gk + 3 < K) v.w += p2[3];
                }
            }
            ra[i] = v;
        }
    };
    auto stA = [&]() {
        #pragma unroll
        for (int i = 0; i < 4; i++) {
            float4 tv = make_float4(to_tf32(ra[i].x), to_tf32(ra[i].y),
                                    to_tf32(ra[i].z), to_tf32(ra[i].w));
            *(float4*)&As[a_m + 32 * i][a_kq * 4] = tv;
        }
    };
    auto ldB = [&](int kb) {
        #pragma unroll
        for (int i = 0; i < 2; i++) {
            const int gk = kb + b_k + 16 * i;
            const int gj = n0 + b_j4 * 4;
            float4 v = make_float4(0.f, 0.f, 0.f, 0.f);
            if (gk < K) {
                const float* p = Bp + (size_t)gk * Nn + gj;
                if (gj + 3 < Nn) v = *(const float4*)p;
                else {
                    if (gj     < Nn) v.x = p[0];
                    if (gj + 1 < Nn) v.y = p[1];
                    if (gj + 2 < Nn) v.z = p[2];
                    if (gj + 3 < Nn) v.w = p[3];
                }
            }
            rb[i] = v;
        }
    };
    auto stB = [&]() {
        #pragma unroll
        for (int i = 0; i < 2; i++) {
            float4 tv = make_float4(to_tf32(rb[i].x), to_tf32(rb[i].y),
                                    to_tf32(rb[i].z), to_tf32(rb[i].w));
            *(float4*)&Bs[b_k + 16 * i][b_j4 * 4] = tv;
        }
    };

    float acc[2][4][4];
    #pragma unroll
    for (int mf = 0; mf < 2; mf++)
        #pragma unroll
        for (int nf = 0; nf < 4; nf++)
            #pragma unroll
            for (int q = 0; q < 4; q++) acc[mf][nf][q] = 0.f;

    ldA(0); ldB(0);
    stA(); stB();
    __syncthreads();

    const int nkt = (K + BK - 1) / BK;
    for (int kt = 0; kt < nkt; kt++) {
        const bool more = (kt + 1 < nkt);
        if (more) { ldA((kt + 1) * BK); ldB((kt + 1) * BK); }

        #pragma unroll
        for (int ks = 0; ks < 4; ks++) {
            const int kof = ks * 8;
            uint32_t af[2][4], bf[4][2];
            #pragma unroll
            for (int mf = 0; mf < 2; mf++) {
                const int r = wm * 32 + mf * 16 + g;
                af[mf][0] = __float_as_uint(As[r    ][kof + t4]);
                af[mf][1] = __float_as_uint(As[r + 8][kof + t4]);
                af[mf][2] = __float_as_uint(As[r    ][kof + t4 + 4]);
                af[mf][3] = __float_as_uint(As[r + 8][kof + t4 + 4]);
            }
            #pragma unroll
            for (int nf = 0; nf < 4; nf++) {
                const int cn = wn * 32 + nf * 8 + g;
                bf[nf][0] = __float_as_uint(Bs[kof + t4    ][cn]);
                bf[nf][1] = __float_as_uint(Bs[kof + t4 + 4][cn]);
            }
            #pragma unroll
            for (int mf = 0; mf < 2; mf++)
                #pragma unroll
                for (int nf = 0; nf < 4; nf++)
                    mma_tf32(acc[mf][nf], af[mf], bf[nf]);
        }
        __syncthreads();
        if (more) { stA(); stB(); __syncthreads(); }
    }

    // epilogue: c0/c1 at (r0, j0..j0+1), c2/c3 at (r0+8, j0..j0+1)
    #pragma unroll
    for (int mf = 0; mf < 2; mf++) {
        const int r0 = m0 + wm * 32 + mf * 16 + g;
        #pragma unroll
        for (int nf = 0; nf < 4; nf++) {
            const int j0 = n0 + wn * 32 + nf * 8 + 2 * t4;
            if (j0 < Nn) {
                const size_t o0 = (size_t)r0 * Nn + j0;
                const size_t o1 = o0 + (size_t)8 * Nn;
                float v0 = acc[mf][nf][0], v1 = acc[mf][nf][1];
                float v2 = acc[mf][nf][2], v3 = acc[mf][nf][3];
                if (EPI == 1) {
                    float2 p0 = *(const float2*)(P + o0);
                    float2 p1 = *(const float2*)(P + o1);
                    v0 += p0.x; v1 += p0.y; v2 += p1.x; v3 += p1.y;
                } else if (EPI == 2) {
                    float b0v = bias[j0], b1v = bias[j0 + 1];
                    v0 += b0v; v1 += b1v; v2 += b0v; v3 += b1v;
                } else if (EPI == 3) {
                    float2 p0 = *(const float2*)(P + o0);
                    float2 p1 = *(const float2*)(P + o1);
                    v0 = p0.x * gelu_t(v0); v1 = p0.y * gelu_t(v1);
                    v2 = p1.x * gelu_t(v2); v3 = p1.y * gelu_t(v3);
                }
                *(float2*)(out + o0) = make_float2(v0, v1);
                *(float2*)(out + o1) = make_float2(v2, v3);
            }
        }
    }
}

// ---------------- host orchestration -------------------------------------------

static float* symaddr(const void* s) {
    void* p = nullptr;
    cudaGetSymbolAddress(&p, s);
    return (float*)p;
}

extern "C" void kernel_launch(void* const* d_in, const int* in_sizes, int n_in,
                              void* d_out, int out_size) {
    const float* x   = (const float*)d_in[0];
    const float* Gc  = (const float*)d_in[3];
    const float* Lc  = (const float*)d_in[4];
    const float* Gt  = (const float*)d_in[5];
    const float* Lt  = (const float*)d_in[6];
    const float* f1r = (const float*)d_in[7];
    const float* f1i = (const float*)d_in[8];
    const float* f2r = (const float*)d_in[9];
    const float* f2i = (const float*)d_in[10];
    const float* fcW = (const float*)d_in[11];
    const float* fcb = (const float*)d_in[12];
    const float* mi1 = (const float*)d_in[13];
    const float* mi2 = (const float*)d_in[14];
    const float* mo1 = (const float*)d_in[15];
    const float* mo2 = (const float*)d_in[16];
    const float* aiq = (const float*)d_in[17];
    const float* aik = (const float*)d_in[18];
    const float* aoq = (const float*)d_in[19];
    const float* aok = (const float*)d_in[20];
    float* out = (float*)d_out;

    float* pA   = symaddr(d_bufA);
    float* pB   = symaddr(d_bufB);
    float* pC   = symaddr(d_bufC);
    float* pdft = symaddr(d_dft);
    float* pidf = symaddr(d_idft);
    float* pM1  = symaddr(d_M1);
    float* pM2  = symaddr(d_M2);
    float* pk1  = symaddr(d_k1);
    float* pk2  = symaddr(d_k2);
    float* pft  = symaddr(d_feat);
    float* pq   = symaddr(d_qb);
    float* pk   = symaddr(d_kb);
    float* pg   = symaddr(d_gt);

    const dim3 T256(256);
    const dim3 G196(4, Mrows / BM);   // Nn=196
    const dim3 G192(3, Mrows / BM);   // Nn=192
    const dim3 G96(2, Mrows / BM);    // Nn=96

    // ---- precompute constant operators (float trig; cheap now) ----
    k_dft<<<(192 * LF + 255) / 256, 256>>>(pdft, pidf);
    k_circ_k<<<(32 * 192 + 255) / 256, 256>>>(f1r, f1i, pk1, 192, 97);
    k_circ_m<<<(32 * 192 * 192 + 255) / 256, 256>>>(pk1, pM1, 192);
    k_circ_k<<<(32 * 96 + 255) / 256, 256>>>(f2r, f2i, pk2, 96, 49);
    k_circ_m<<<(32 * 96 * 96 + 255) / 256, 256>>>(pk2, pM2, 96);

    // ---- freq_attn_in: F = rfft(x); mix; x_c = x + irfft(mix) ----
    gemm_tc<0, false, false, false><<<G196, T256>>>(x, nullptr, nullptr, pdft,
                                                    nullptr, nullptr, pA, 192, LF);
    k_mix<<<16 * 512, 256>>>(pA, pB, Gc, Lc, Gt, Lt);
    gemm_tc<1, false, false, false><<<G192, T256>>>(pB, nullptr, nullptr, pidf,
                                                    x, nullptr, pC, LF, 192);

    // ---- input layer 0: gmlp then gate (gate folded into next GEMM loads) ----
    gemm_tc<0, false, false, false><<<G192, T256>>>(pC, nullptr, nullptr, mi1,
                                                    nullptr, nullptr, pA, 192, 192);
    gemm_tc<3, false, false, false><<<G192, T256>>>(pC, nullptr, nullptr, mi2,
                                                    pA, nullptr, pB, 192, 192);
    k_feat<<<512, 192>>>(pB, pft, 192);
    k_qk<<<16, 256>>>(pft, aiq, aik, pq, pk, 192);
    k_gate<<<16, 192>>>(pq, pk, pg, 192);

    // ---- input layer 1 (A scaled by 1+g0) ----
    gemm_tc<0, false, false, true><<<G192, T256>>>(pB, nullptr, pg, mi1 + 192 * 192,
                                                   nullptr, nullptr, pC, 192, 192);
    gemm_tc<3, false, false, true><<<G192, T256>>>(pB, nullptr, pg, mi2 + 192 * 192,
                                                   pC, nullptr, pA, 192, 192);
    k_feat<<<512, 192>>>(pA, pft, 192);
    k_qk<<<16, 256>>>(pft, aiq + 32 * 64, aik + 32 * 64, pq, pk, 192);
    k_gate<<<16, 192>>>(pq, pk, pg, 192);

    // ---- fconv1: h_x = circconv(x + x_c*(1+g1), M1_c) ----
    gemm_tc<0, true, true, true><<<G192, T256>>>(pA, x, pg, pM1,
                                                 nullptr, nullptr, pB, 192, 192);

    // ---- fc_idp: h_y = h_x @ Wfc + b ----
    gemm_tc<2, false, false, false><<<G96, T256>>>(pB, nullptr, nullptr, fcW,
                                                   nullptr, fcb, pC, 192, 96);

    // ---- output layer 0 ----
    gemm_tc<0, false, false, false><<<G96, T256>>>(pC, nullptr, nullptr, mo1,
                                                   nullptr, nullptr, pA, 96, 96);
    gemm_tc<3, false, false, false><<<G96, T256>>>(pC, nullptr, nullptr, mo2,
                                                   pA, nullptr, pB, 96, 96);
    k_feat<<<512, 96>>>(pB, pft, 96);
    k_qk<<<16, 256>>>(pft, aoq, aok, pq, pk, 96);
    k_gate<<<16, 96>>>(pq, pk, pg, 96);

    // ---- output layer 1 (A scaled by 1+g2); second GEMM writes bufA in place ----
    gemm_tc<0, false, false, true><<<G96, T256>>>(pB, nullptr, pg, mo1 + 96 * 96,
                                                  nullptr, nullptr, pA, 96, 96);
    gemm_tc<3, false, false, true><<<G96, T256>>>(pB, nullptr, pg, mo2 + 96 * 96,
                                                  pA, nullptr, pA, 96, 96);
    k_feat<<<512, 96>>>(pA, pft, 96);
    k_qk<<<16, 256>>>(pft, aoq + 32 * 64, aok + 32 * 64, pq, pk, 96);
    k_gate<<<16, 96>>>(pq, pk, pg, 96);

    // ---- final fconv2: out = circconv(h_y + y_c*(1+g3), M2_c) ----
    gemm_tc<0, true, true, true><<<G96, T256>>>(pA, pC, pg, pM2,
                                                nullptr, nullptr, out, 96, 96);
}

// round 16
// speedup vs baseline: 1.7234x; 1.0293x over previous
#include <cuda_runtime.h>
#include <cstdint>
#include <math.h>

#ifndef M_PI
#define M_PI 3.14159265358979323846
#endif

// Problem dims: B=16, C=32, N=512, T_IN=192, T_OUT=96, L_IN=97, L_OUT=49, E=64
constexpr int Mrows = 16 * 32 * 512;   // 262144 rows
constexpr int LF = 196;                // padded spectral width (194 -> 196 for 16B alignment)

// ---------------- scratch (__device__ globals; no allocation allowed) ----------
__device__ float d_bufA[(size_t)Mrows * LF];    // ~205 MB
__device__ float d_bufB[(size_t)Mrows * LF];    // ~205 MB
__device__ float d_bufC[(size_t)Mrows * 192];   // ~201 MB
__device__ float d_dft[192 * LF];
__device__ float d_idft[LF * 192];
__device__ float d_M1[32 * 192 * 192];
__device__ float d_M2[32 * 96 * 96];
__device__ float d_k1[32 * 192];
__device__ float d_k2[32 * 96];
__device__ float d_feat[16 * 192 * 32];
__device__ float d_qb[16 * 192 * 64];
__device__ float d_kb[16 * 192 * 64];
__device__ float d_gt[16 * 192];

__device__ __forceinline__ float gelu_t(float x) {
    // jax.nn.gelu default: tanh approximation
    float x3 = x * x * x;
    float t = tanhf(0.7978845608028654f * (x + 0.044715f * x3));
    return 0.5f * x * (1.0f + t);
}

__device__ __forceinline__ float to_tf32(float x) {
    uint32_t u;
    asm("cvt.rna.tf32.f32 %0, %1;" : "=r"(u) : "f"(x));
    return __uint_as_float(u);
}

__device__ __forceinline__ void mma_tf32(float* c, const uint32_t* a, const uint32_t* b) {
    asm volatile(
        "mma.sync.aligned.m16n8k8.row.col.f32.tf32.tf32.f32 "
        "{%0,%1,%2,%3}, {%4,%5,%6,%7}, {%8,%9}, {%0,%1,%2,%3};"
        : "+f"(c[0]), "+f"(c[1]), "+f"(c[2]), "+f"(c[3])
        : "r"(a[0]), "r"(a[1]), "r"(a[2]), "r"(a[3]), "r"(b[0]), "r"(b[1]));
}

// ---------------- precompute kernels --------------------------------------------

__global__ void k_dft(float* dft, float* idft) {
    int i = blockIdx.x * 256 + threadIdx.x;
    if (i >= 192 * LF) return;
    {
        int s = i / LF, h2 = i % LF;
        float v = 0.f;
        if (h2 < 194) {
            int h = (h2 < 97) ? h2 : h2 - 97;
            float fr = (float)(2 * ((s * h) % 192)) / 192.0f;
            float sn, cs; sincospif(fr, &sn, &cs);
            v = (h2 < 97) ? cs : -sn;
        }
        dft[i] = v;
    }
    {
        int r = i / 192, t = i % 192;     // LF*192 == 192*LF elements
        float v = 0.f;
        if (r < 194) {
            int h = (r < 97) ? r : r - 97;
            float ch = (h == 0 || h == 96) ? (1.f / 192.f) : (2.f / 192.f);
            float fr = (float)(2 * ((h * t) % 192)) / 192.0f;
            float sn, cs; sincospif(fr, &sn, &cs);
            v = (r < 97) ? ch * cs : -ch * sn;
        }
        idft[i] = v;
    }
}

__global__ void k_circ_k(const float* __restrict__ Wr, const float* __restrict__ Wi,
                         float* __restrict__ kk, int T, int L) {
    int i = blockIdx.x * 256 + threadIdx.x;
    if (i >= 32 * T) return;
    int c = i / T, t = i % T;
    float s = 0.f;
    for (int h = 0; h < L; h++) {
        float ch = (h == 0 || h == L - 1) ? 1.f / (float)T : 2.f / (float)T;
        float fr = (float)(2 * ((h * t) % T)) / (float)T;
        float sn, cs; sincospif(fr, &sn, &cs);
        s += ch * (Wr[c * L + h] * cs - Wi[c * L + h] * sn);
    }
    kk[i] = s;
}

__global__ void k_circ_m(const float* __restrict__ kk, float* __restrict__ Mm, int T) {
    int i = blockIdx.x * 256 + threadIdx.x;
    if (i >= 32 * T * T) return;
    int c = i / (T * T); int r = i % (T * T); int s = r / T, t = r % T;
    Mm[i] = kk[c * T + ((t - s + T) % T)];
}

// ---------------- spectrum channel-mix (freq_attn_in), stride LF=196 -------------
__global__ void k_mix(const float* __restrict__ F, float* __restrict__ G,
                      const float* __restrict__ Gc, const float* __restrict__ Lc,
                      const float* __restrict__ Gt, const float* __restrict__ Lt) {
    __shared__ float sF[32][195];
    __shared__ float sGc[32][32];
    __shared__ float sGt[32][32];
    int b = blockIdx.x >> 9;
    int n = blockIdx.x & 511;
    int tid = threadIdx.x;
    for (int idx = tid; idx < 32 * 194; idx += 256) {
        int c = idx / 194, h = idx % 194;
        sF[c][h] = F[(((size_t)b * 32 + c) * 512 + n) * LF + h];
    }
    for (int idx = tid; idx < 1024; idx += 256) {
        sGc[idx >> 5][idx & 31] = Gc[idx];
        sGt[idx >> 5][idx & 31] = Gt[idx];
    }
    __syncthreads();
    for (int o = tid; o < 32 * LF; o += 256) {
        int l = o / LF, h2 = o % LF;
        float s = 0.f;
        if (h2 < 97) {
            #pragma unroll 8
            for (int c = 0; c < 32; c++) s = fmaf(sGc[c][l], sF[c][h2], s);
            s *= Lc[l * 97 + h2];
        } else if (h2 < 194) {
            int h = h2 - 97;
            #pragma unroll 8
            for (int c = 0; c < 32; c++) s = fmaf(sGt[c][l], sF[c][h2], s);
            s *= Lt[l * 97 + h];
        }
        G[(((size_t)b * 32 + l) * 512 + n) * LF + h2] = s;
    }
}

// ---------------- attention-gate helpers -----------------------------------------

__global__ void k_feat(const float* __restrict__ Z, float* __restrict__ feat, int T) {
    int b = blockIdx.x >> 5, c = blockIdx.x & 31;
    int t = threadIdx.x;
    const float* p = Z + ((size_t)(b * 32 + c) * 512) * T + t;
    float s = 0.f;
    #pragma unroll 4
    for (int n = 0; n < 512; n++) s += p[(size_t)n * T];
    feat[((size_t)b * T + t) * 32 + c] = s * (1.0f / 512.0f);
}

__global__ void k_qk(const float* __restrict__ feat, const float* __restrict__ Wq,
                     const float* __restrict__ Wk, float* __restrict__ qo,
                     float* __restrict__ ko, int T) {
    int b = blockIdx.x;
    __shared__ float sW[32][128];
    int tid = threadIdx.x;
    for (int i = tid; i < 2048; i += 256) {
        int c = i >> 6, e = i & 63;
        sW[c][e] = Wq[i]; sW[c][64 + e] = Wk[i];
    }
    __syncthreads();
    for (int o = tid; o < T * 64; o += 256) {
        int t = o >> 6, e = o & 63;
        const float* f = feat + ((size_t)b * T + t) * 32;
        float sq = 0.f, sk = 0.f;
        #pragma unroll
        for (int c = 0; c < 32; c++) {
            float fv = f[c];
            sq = fmaf(fv, sW[c][e], sq);
            sk = fmaf(fv, sW[c][64 + e], sk);
        }
        qo[(size_t)b * T * 64 + o] = sq;
        ko[(size_t)b * T * 64 + o] = sk;
    }
}

__global__ void k_gate(const float* __restrict__ qv, const float* __restrict__ kv,
                       float* __restrict__ g, int T) {
    int b = blockIdx.x, t = threadIdx.x;
    float qr[64];
    const float* qp = qv + ((size_t)b * T + t) * 64;
    #pragma unroll
    for (int e = 0; e < 64; e++) qr[e] = qp[e];
    const float* kb = kv + (size_t)b * T * 64;
    float mx = -3.0e38f, sum = 0.f, sd = 0.f;
    for (int j = 0; j < T; j++) {
        float s = 0.f;
        #pragma unroll
        for (int e = 0; e < 64; e++) s = fmaf(qr[e], kb[j * 64 + e], s);
        s *= 0.125f;
        if (j == t) sd = s;
        float nmx = fmaxf(mx, s);
        sum = sum * expf(mx - nmx) + expf(s - nmx);
        mx = nmx;
    }
    float w = expf(sd - mx) / sum;
    g[b * T + t] = gelu_t(w);
}

// ---------------- tf32 tensor-core fused GEMM (double-buffered, optional DUAL) ----
// Single: out = epi( a(m,:) @ B )
// DUAL  : out = (a @ B) * gelu(a @ B2)   (gmlp fused: value * gelu(gate))
//   a(m,k) = A[m,k] * (HAS_GATE ? 1+g[b,k] : 1) + (HAS_A2 ? A2[m,k] : 0)
//   PER_CH_B: B += c*K*Nn (c from row block; 128 rows share (b,c))
//   EPI: 0 none | 1 +P | 2 +bias[j]   (ignored when DUAL)
constexpr int BM = 128, BN = 64, BK = 32;
constexpr int AS_F = 128 * 36;   // floats per A-stage
constexpr int BS_F = 32 * 72;    // floats per B-stage
constexpr size_t SMEM_SINGLE = (size_t)(2 * AS_F + 2 * BS_F + 224) * 4;
constexpr size_t SMEM_DUAL   = (size_t)(2 * AS_F + 4 * BS_F + 224) * 4;

template<int EPI, bool HAS_A2, bool PER_CH_B, bool HAS_GATE, bool DUAL>
__global__ __launch_bounds__(256)
void gemm_tc(const float* __restrict__ A, const float* __restrict__ A2,
             const float* __restrict__ gate,
             const float* __restrict__ Bm, const float* __restrict__ Bm2,
             const float* __restrict__ P, const float* __restrict__ bias,
             float* __restrict__ out, int K, int Nn) {
    extern __shared__ float sm[];
    float* AsB  = sm;                       // [2][128][36]
    float* BsB  = sm + 2 * AS_F;            // [2][32][72]
    float* Bs2B = BsB + 2 * BS_F;           // [2][32][72] (DUAL only)
    float* sAk  = DUAL ? (Bs2B + 2 * BS_F) : (BsB + 2 * BS_F);

    const int tid = threadIdx.x;
    const int m0 = blockIdx.y * BM;
    const int n0 = blockIdx.x * BN;
    const int bc = m0 >> 9;
    const int c  = bc & 31;
    const int b  = bc >> 5;

    if (HAS_GATE) {
        for (int k2 = tid; k2 < K; k2 += 256) sAk[k2] = 1.f + gate[b * K + k2];
        __syncthreads();
    }
    const float* Bp  = PER_CH_B ? (Bm + (size_t)c * K * Nn) : Bm;
    const float* Bp2 = DUAL ? Bm2 : nullptr;

    const int lane = tid & 31, warp = tid >> 5;
    const int wm = warp >> 1, wn = warp & 1;       // 4 x 2 warp grid, warp tile 32x32
    const int g = lane >> 2, t4 = lane & 3;

    const int a_kq = tid & 7, a_m = tid >> 3;      // A loader: rows a_m+32i, float4 at k=a_kq*4
    const int b_j4 = tid & 15, b_k = tid >> 4;     // B loader: rows b_k+16i, float4 at j=b_j4*4

    float4 ra[4];
    float4 rb[2], rb2[2];

    auto ldA = [&](int kb) {
        const int gk = kb + a_kq * 4;
        const bool full = (gk + 3 < K);
        #pragma unroll
        for (int i = 0; i < 4; i++) {
            const size_t row = (size_t)(m0 + a_m + 32 * i);
            const float* p = A + row * K + gk;
            float4 v = make_float4(0.f, 0.f, 0.f, 0.f);
            if (full) v = *(const float4*)p;
            else {
                if (gk     < K) v.x = p[0];
                if (gk + 1 < K) v.y = p[1];
                if (gk + 2 < K) v.z = p[2];
                if (gk + 3 < K) v.w = p[3];
            }
            if (HAS_GATE) {
                if (full) { v.x *= sAk[gk]; v.y *= sAk[gk+1]; v.z *= sAk[gk+2]; v.w *= sAk[gk+3]; }
                else {
                    if (gk     < K) v.x *= sAk[gk];
                    if (gk + 1 < K) v.y *= sAk[gk+1];
                    if (gk + 2 < K) v.z *= sAk[gk+2];
                    if (gk + 3 < K) v.w *= sAk[gk+3];
                }
            }
            if (HAS_A2) {
                const float* p2 = A2 + row * K + gk;
                if (full) { float4 w = *(const float4*)p2; v.x += w.x; v.y += w.y; v.z += w.z; v.w += w.w; }
                else {
                    if (gk     < K) v.x += p2[0];
                    if (gk + 1 < K) v.y += p2[1];
                    if (gk + 2 < K) v.z += p2[2];
                    if (gk + 3 < K) v.w += p2[3];
                }
            }
            ra[i] = v;
        }
    };
    auto stA = [&](int buf) {
        float* dst = AsB + buf * AS_F;
        #pragma unroll
        for (int i = 0; i < 4; i++) {
            float4 tv = make_float4(to_tf32(ra[i].x), to_tf32(ra[i].y),
                                    to_tf32(ra[i].z), to_tf32(ra[i].w));
            *(float4*)&dst[(a_m + 32 * i) * 36 + a_kq * 4] = tv;
        }
    };
    auto ldBone = [&](int kb, const float* BB, float4* r) {
        #pragma unroll
        for (int i = 0; i < 2; i++) {
            const int gk = kb + b_k + 16 * i;
            const int gj = n0 + b_j4 * 4;
            float4 v = make_float4(0.f, 0.f, 0.f, 0.f);
            if (gk < K) {
                const float* p = BB + (size_t)gk * Nn + gj;
                if (gj + 3 < Nn) v = *(const float4*)p;
                else {
                    if (gj     < Nn) v.x = p[0];
                    if (gj + 1 < Nn) v.y = p[1];
                    if (gj + 2 < Nn) v.z = p[2];
                    if (gj + 3 < Nn) v.w = p[3];
                }
            }
            r[i] = v;
        }
    };
    auto stBone = [&](int buf, float* base, const float4* r) {
        float* dst = base + buf * BS_F;
        #pragma unroll
        for (int i = 0; i < 2; i++) {
            float4 tv = make_float4(to_tf32(r[i].x), to_tf32(r[i].y),
                                    to_tf32(r[i].z), to_tf32(r[i].w));
            *(float4*)&dst[(b_k + 16 * i) * 72 + b_j4 * 4] = tv;
        }
    };

    float accv[2][4][4];
    float accg[DUAL ? 2 : 1][DUAL ? 4 : 1][4];
    #pragma unroll
    for (int mf = 0; mf < 2; mf++)
        #pragma unroll
        for (int nf = 0; nf < 4; nf++)
            #pragma unroll
            for (int q = 0; q < 4; q++) {
                accv[mf][nf][q] = 0.f;
                if (DUAL) accg[mf][nf][q] = 0.f;
            }

    auto do_mma = [&](int buf) {
        const float* As_  = AsB + buf * AS_F;
        const float* Bs_  = BsB + buf * BS_F;
        const float* Bs2_ = Bs2B + buf * BS_F;
        #pragma unroll
        for (int ks = 0; ks < 4; ks++) {
            const int kof = ks * 8;
            uint32_t af[2][4], bf[4][2], bf2[4][2];
            #pragma unroll
            for (int mf = 0; mf < 2; mf++) {
                const int r = wm * 32 + mf * 16 + g;
                af[mf][0] = __float_as_uint(As_[r * 36 + kof + t4]);
                af[mf][1] = __float_as_uint(As_[(r + 8) * 36 + kof + t4]);
                af[mf][2] = __float_as_uint(As_[r * 36 + kof + t4 + 4]);
                af[mf][3] = __float_as_uint(As_[(r + 8) * 36 + kof + t4 + 4]);
            }
            #pragma unroll
            for (int nf = 0; nf < 4; nf++) {
                const int cn = wn * 32 + nf * 8 + g;
                bf[nf][0] = __float_as_uint(Bs_[(kof + t4) * 72 + cn]);
                bf[nf][1] = __float_as_uint(Bs_[(kof + t4 + 4) * 72 + cn]);
                if (DUAL) {
                    bf2[nf][0] = __float_as_uint(Bs2_[(kof + t4) * 72 + cn]);
                    bf2[nf][1] = __float_as_uint(Bs2_[(kof + t4 + 4) * 72 + cn]);
                }
            }
            #pragma unroll
            for (int mf = 0; mf < 2; mf++)
                #pragma unroll
                for (int nf = 0; nf < 4; nf++) {
                    mma_tf32(accv[mf][nf], af[mf], bf[nf]);
                    if (DUAL) mma_tf32(accg[mf][nf], af[mf], bf2[nf]);
                }
        }
    };

    // prologue: stage 0
    ldA(0); ldBone(0, Bp, rb); if (DUAL) ldBone(0, Bp2, rb2);
    stA(0); stBone(0, BsB, rb); if (DUAL) stBone(0, Bs2B, rb2);
    __syncthreads();

    const int nkt = (K + BK - 1) / BK;
    for (int kt = 0; kt < nkt; kt++) {
        const int cur = kt & 1, nxt = cur ^ 1;
        const bool more = (kt + 1 < nkt);
        if (more) {
            const int kb = (kt + 1) * BK;
            ldA(kb); ldBone(kb, Bp, rb); if (DUAL) ldBone(kb, Bp2, rb2);
        }
        do_mma(cur);
        if (more) {
            stA(nxt); stBone(nxt, BsB, rb); if (DUAL) stBone(nxt, Bs2B, rb2);
        }
        __syncthreads();
    }

    // epilogue: c0/c1 at (r0, j0..j0+1), c2/c3 at (r0+8, j0..j0+1)
    #pragma unroll
    for (int mf = 0; mf < 2; mf++) {
        const int r0 = m0 + wm * 32 + mf * 16 + g;
        #pragma unroll
        for (int nf = 0; nf < 4; nf++) {
            const int j0 = n0 + wn * 32 + nf * 8 + 2 * t4;
            if (j0 < Nn) {
                const size_t o0 = (size_t)r0 * Nn + j0;
                const size_t o1 = o0 + (size_t)8 * Nn;
                float v0 = accv[mf][nf][0], v1 = accv[mf][nf][1];
                float v2 = accv[mf][nf][2], v3 = accv[mf][nf][3];
                if (DUAL) {
                    v0 *= gelu_t(accg[mf][nf][0]); v1 *= gelu_t(accg[mf][nf][1]);
                    v2 *= gelu_t(accg[mf][nf][2]); v3 *= gelu_t(accg[mf][nf][3]);
                } else if (EPI == 1) {
                    float2 p0 = *(const float2*)(P + o0);
                    float2 p1 = *(const float2*)(P + o1);
                    v0 += p0.x; v1 += p0.y; v2 += p1.x; v3 += p1.y;
                } else if (EPI == 2) {
                    float b0v = bias[j0], b1v = bias[j0 + 1];
                    v0 += b0v; v1 += b1v; v2 += b0v; v3 += b1v;
                }
                *(float2*)(out + o0) = make_float2(v0, v1);
                *(float2*)(out + o1) = make_float2(v2, v3);
            }
        }
    }
}

// ---------------- host orchestration ---------------------------------------------

static float* symaddr(const void* s) {
    void* p = nullptr;
    cudaGetSymbolAddress(&p, s);
    return (float*)p;
}

extern "C" void kernel_launch(void* const* d_in, const int* in_sizes, int n_in,
                              void* d_out, int out_size) {
    const float* x   = (const float*)d_in[0];
    const float* Gc  = (const float*)d_in[3];
    const float* Lc  = (const float*)d_in[4];
    const float* Gt  = (const float*)d_in[5];
    const float* Lt  = (const float*)d_in[6];
    const float* f1r = (const float*)d_in[7];
    const float* f1i = (const float*)d_in[8];
    const float* f2r = (const float*)d_in[9];
    const float* f2i = (const float*)d_in[10];
    const float* fcW = (const float*)d_in[11];
    const float* fcb = (const float*)d_in[12];
    const float* mi1 = (const float*)d_in[13];
    const float* mi2 = (const float*)d_in[14];
    const float* mo1 = (const float*)d_in[15];
    const float* mo2 = (const float*)d_in[16];
    const float* aiq = (const float*)d_in[17];
    const float* aik = (const float*)d_in[18];
    const float* aoq = (const float*)d_in[19];
    const float* aok = (const float*)d_in[20];
    float* out = (float*)d_out;

    float* pA   = symaddr(d_bufA);
    float* pB   = symaddr(d_bufB);
    float* pC   = symaddr(d_bufC);
    float* pdft = symaddr(d_dft);
    float* pidf = symaddr(d_idft);
    float* pM1  = symaddr(d_M1);
    float* pM2  = symaddr(d_M2);
    float* pk1  = symaddr(d_k1);
    float* pk2  = symaddr(d_k2);
    float* pft  = symaddr(d_feat);
    float* pq   = symaddr(d_qb);
    float* pk   = symaddr(d_kb);
    float* pg   = symaddr(d_gt);

    // dynamic smem limits (idempotent)
    cudaFuncSetAttribute((const void*)gemm_tc<0, false, false, false, false>,
                         cudaFuncAttributeMaxDynamicSharedMemorySize, (int)SMEM_SINGLE);
    cudaFuncSetAttribute((const void*)gemm_tc<1, false, false, false, false>,
                         cudaFuncAttributeMaxDynamicSharedMemorySize, (int)SMEM_SINGLE);
    cudaFuncSetAttribute((const void*)gemm_tc<2, false, false, false, false>,
                         cudaFuncAttributeMaxDynamicSharedMemorySize, (int)SMEM_SINGLE);
    cudaFuncSetAttribute((const void*)gemm_tc<0, true, true, true, false>,
                         cudaFuncAttributeMaxDynamicSharedMemorySize, (int)SMEM_SINGLE);
    cudaFuncSetAttribute((const void*)gemm_tc<0, false, false, false, true>,
                         cudaFuncAttributeMaxDynamicSharedMemorySize, (int)SMEM_DUAL);
    cudaFuncSetAttribute((const void*)gemm_tc<0, false, false, true, true>,
                         cudaFuncAttributeMaxDynamicSharedMemorySize, (int)SMEM_DUAL);

    const dim3 T256(256);
    const dim3 G196(4, Mrows / BM);   // Nn=196
    const dim3 G192(3, Mrows / BM);   // Nn=192
    const dim3 G96(2, Mrows / BM);    // Nn=96

    // ---- precompute constant operators ----
    k_dft<<<(192 * LF + 255) / 256, 256>>>(pdft, pidf);
    k_circ_k<<<(32 * 192 + 255) / 256, 256>>>(f1r, f1i, pk1, 192, 97);
    k_circ_m<<<(32 * 192 * 192 + 255) / 256, 256>>>(pk1, pM1, 192);
    k_circ_k<<<(32 * 96 + 255) / 256, 256>>>(f2r, f2i, pk2, 96, 49);
    k_circ_m<<<(32 * 96 * 96 + 255) / 256, 256>>>(pk2, pM2, 96);

    // ---- freq_attn_in: F = rfft(x); mix; x_c = x + irfft(mix) ----
    gemm_tc<0, false, false, false, false><<<G196, T256, SMEM_SINGLE>>>(
        x, nullptr, nullptr, pdft, nullptr, nullptr, nullptr, pA, 192, LF);
    k_mix<<<16 * 512, 256>>>(pA, pB, Gc, Lc, Gt, Lt);
    gemm_tc<1, false, false, false, false><<<G192, T256, SMEM_SINGLE>>>(
        pB, nullptr, nullptr, pidf, nullptr, x, nullptr, pC, LF, 192);

    // ---- input layer 0: fused gmlp, then gate ----
    gemm_tc<0, false, false, false, true><<<G192, T256, SMEM_DUAL>>>(
        pC, nullptr, nullptr, mi1, mi2, nullptr, nullptr, pB, 192, 192);
    k_feat<<<512, 192>>>(pB, pft, 192);
    k_qk<<<16, 256>>>(pft, aiq, aik, pq, pk, 192);
    k_gate<<<16, 192>>>(pq, pk, pg, 192);

    // ---- input layer 1: fused gmlp with gate fold, then gate ----
    gemm_tc<0, false, false, true, true><<<G192, T256, SMEM_DUAL>>>(
        pB, nullptr, pg, mi1 + 192 * 192, mi2 + 192 * 192, nullptr, nullptr, pC, 192, 192);
    k_feat<<<512, 192>>>(pC, pft, 192);
    k_qk<<<16, 256>>>(pft, aiq + 32 * 64, aik + 32 * 64, pq, pk, 192);
    k_gate<<<16, 192>>>(pq, pk, pg, 192);

    // ---- fconv1: h_x = circconv(x + x_c*(1+g1), M1_c) ----
    gemm_tc<0, true, true, true, false><<<G192, T256, SMEM_SINGLE>>>(
        pC, x, pg, pM1, nullptr, nullptr, nullptr, pB, 192, 192);

    // ---- fc_idp: h_y = h_x @ Wfc + b  (h_y kept in pA until the end) ----
    gemm_tc<2, false, false, false, false><<<G96, T256, SMEM_SINGLE>>>(
        pB, nullptr, nullptr, fcW, nullptr, nullptr, fcb, pA, 192, 96);

    // ---- output layer 0 ----
    gemm_tc<0, false, false, false, true><<<G96, T256, SMEM_DUAL>>>(
        pA, nullptr, nullptr, mo1, mo2, nullptr, nullptr, pB, 96, 96);
    k_feat<<<512, 96>>>(pB, pft, 96);
    k_qk<<<16, 256>>>(pft, aoq, aok, pq, pk, 96);
    k_gate<<<16, 96>>>(pq, pk, pg, 96);

    // ---- output layer 1 ----
    gemm_tc<0, false, false, true, true><<<G96, T256, SMEM_DUAL>>>(
        pB, nullptr, pg, mo1 + 96 * 96, mo2 + 96 * 96, nullptr, nullptr, pC, 96, 96);
    k_feat<<<512, 96>>>(pC, pft, 96);
    k_qk<<<16, 256>>>(pft, aoq + 32 * 64, aok + 32 * 64, pq, pk, 96);
    k_gate<<<16, 96>>>(pq, pk, pg, 96);

    // ---- final fconv2: out = circconv(h_y + y_c*(1+g3), M2_c) ----
    gemm_tc<0, true, true, true, false><<<G96, T256, SMEM_SINGLE>>>(
        pC, pA, pg, pM2, nullptr, nullptr, nullptr, out, 96, 96);
}